// round 1
// baseline (speedup 1.0000x reference)
#include <cuda_runtime.h>

// ---------------- problem constants (fixed shapes) ----------------
#define NN      50000
#define E_REAL  800000
#define E_TOT   850000      // + N self loops
#define INF_    128
#define HF      64
#define NHEADS  4
#define GG      256
#define OUTF    326000
#define NEGS    0.2f

// ---------------- scratch (__device__ globals; no allocs) ----------------
__device__ float    g_h   [NN * HF];                 // 12.8 MB
__device__ float    g_z   [(size_t)NN * 256];        // 51.2 MB
__device__ float    g_as  [NN * 4];
__device__ float    g_ad  [NN * 4];
__device__ unsigned g_menc[NN * 4];
__device__ float    g_den [NN * 4];                  // becomes 1/denom
__device__ float    g_wbuf[(size_t)E_TOT * 4];       // 13.6 MB
__device__ float    g_hacc[NN * HF];                 // 12.8 MB
__device__ float    g_gsum[GG * HF];
__device__ float    g_cnt [GG];
__device__ float    g_pool[GG * HF];

// ---------------- helpers ----------------
__device__ __forceinline__ float lrelu(float v) { return v > 0.f ? v : NEGS * v; }

// monotonic float->uint encoding so native atomicMax works for any sign
__device__ __forceinline__ unsigned fenc(float f) {
    unsigned u = __float_as_uint(f);
    return (u & 0x80000000u) ? ~u : (u | 0x80000000u);
}
__device__ __forceinline__ float fdec(unsigned u) {
    return (u & 0x80000000u) ? __uint_as_float(u ^ 0x80000000u) : __uint_as_float(~u);
}

__device__ __forceinline__ void red_add_v4(float* p, float4 v) {
    asm volatile("red.global.add.v4.f32 [%0], {%1,%2,%3,%4};"
                 :: "l"(p), "f"(v.x), "f"(v.y), "f"(v.z), "f"(v.w) : "memory");
}

__device__ __forceinline__ void edge_sd(int e, const int* __restrict__ ei, int& s, int& d) {
    if (e < E_REAL) { s = ei[e]; d = ei[E_REAL + e]; }
    else            { s = e - E_REAL; d = s; }
}

__device__ __forceinline__ float4 edge_e(int s, int d) {
    float4 a = *reinterpret_cast<const float4*>(g_as + s * 4);
    float4 b = *reinterpret_cast<const float4*>(g_ad + d * 4);
    float4 r;
    r.x = lrelu(a.x + b.x); r.y = lrelu(a.y + b.y);
    r.z = lrelu(a.z + b.z); r.w = lrelu(a.w + b.w);
    return r;
}

// ---------------- kernels ----------------

// h = x @ emb_w^T + emb_b    (N x 128 -> N x 64). 4 nodes / 256-thread block.
__global__ __launch_bounds__(256) void k_embed(const float* __restrict__ x,
                                               const float* __restrict__ w,
                                               const float* __restrict__ b) {
    __shared__ float ws[64 * 129];   // +1 pad: conflict-free
    __shared__ float xs[4 * 128];
    int tid = threadIdx.x;
    for (int i = tid; i < 64 * 128; i += 256)
        ws[(i >> 7) * 129 + (i & 127)] = w[i];
    int n0 = blockIdx.x * 4;
    for (int i = tid; i < 4 * 128; i += 256)
        xs[i] = x[n0 * 128 + i];
    __syncthreads();
    int j = tid & 63, ln = tid >> 6;
    const float* wr = ws + j * 129;
    const float* xr = xs + ln * 128;
    float acc = b[j];
#pragma unroll 16
    for (int k = 0; k < 128; k++) acc = fmaf(xr[k], wr[k], acc);
    g_h[(n0 + ln) * 64 + j] = acc;
}

// z = h @ lin_w^T  (N x 64 -> N x 256).  blockIdx.y picks output half (128 cols),
// block processes 40 nodes with weights staged in smem.
__global__ __launch_bounds__(128) void k_zgemm(const float* __restrict__ lw) {
    __shared__ float ws[128 * 65];
    __shared__ float hs[40 * 64];
    int tid = threadIdx.x;
    int obase = blockIdx.y * 128;
    for (int i = tid; i < 128 * 64; i += 128)
        ws[(i >> 6) * 65 + (i & 63)] = lw[obase * 64 + i];
    int n0 = blockIdx.x * 40;
    for (int i = tid; i < 40 * 64; i += 128)
        hs[i] = g_h[n0 * 64 + i];
    __syncthreads();
    const float* wr = ws + tid * 65;
    for (int nl = 0; nl < 40; nl++) {
        const float* hr = hs + nl * 64;
        float acc = 0.f;
#pragma unroll
        for (int k = 0; k < 64; k++) acc = fmaf(hr[k], wr[k], acc);
        g_z[(size_t)(n0 + nl) * 256 + obase + tid] = acc;
    }
}

// per-node attention logits: a_s[n,h] = <z[n,h,:], att_src[h,:]>, same for dst.
// one warp per node.
__global__ __launch_bounds__(256) void k_scores(const float* __restrict__ aw_s,
                                                const float* __restrict__ aw_d) {
    int wid  = (blockIdx.x * 256 + threadIdx.x) >> 5;
    int lane = threadIdx.x & 31;
    if (wid >= NN) return;
    const float* zr = g_z + (size_t)wid * 256;
#pragma unroll
    for (int h = 0; h < 4; h++) {
        float z0 = zr[h * 64 + lane], z1 = zr[h * 64 + 32 + lane];
        float s = z0 * aw_s[h * 64 + lane] + z1 * aw_s[h * 64 + 32 + lane];
        float d = z0 * aw_d[h * 64 + lane] + z1 * aw_d[h * 64 + 32 + lane];
#pragma unroll
        for (int o = 16; o; o >>= 1) {
            s += __shfl_down_sync(0xffffffffu, s, o);
            d += __shfl_down_sync(0xffffffffu, d, o);
        }
        if (!lane) { g_as[wid * 4 + h] = s; g_ad[wid * 4 + h] = d; }
    }
}

// zero accumulators for the layer  (grid covers exactly N*64)
__global__ __launch_bounds__(256) void k_init() {
    int i = blockIdx.x * 256 + threadIdx.x;
    g_hacc[i] = 0.f;
    if (i < NN * 4) { g_menc[i] = 0u; g_den[i] = 0.f; }
}

// pass 1: segment max over dst (encoded atomicMax)
__global__ __launch_bounds__(256) void k_emax(const int* __restrict__ ei) {
    int e = blockIdx.x * 256 + threadIdx.x;
    if (e >= E_TOT) return;
    int s, d; edge_sd(e, ei, s, d);
    float4 ev = edge_e(s, d);
    unsigned* mp = g_menc + d * 4;
    atomicMax(mp + 0, fenc(ev.x));
    atomicMax(mp + 1, fenc(ev.y));
    atomicMax(mp + 2, fenc(ev.z));
    atomicMax(mp + 3, fenc(ev.w));
}

// pass 2: w = exp(e - m[dst]); store w; segment-sum denom (vector red)
__global__ __launch_bounds__(256) void k_esum(const int* __restrict__ ei) {
    int e = blockIdx.x * 256 + threadIdx.x;
    if (e >= E_TOT) return;
    int s, d; edge_sd(e, ei, s, d);
    float4 ev = edge_e(s, d);
    const unsigned* mp = g_menc + d * 4;
    float4 w;
    w.x = __expf(ev.x - fdec(mp[0]));
    w.y = __expf(ev.y - fdec(mp[1]));
    w.z = __expf(ev.z - fdec(mp[2]));
    w.w = __expf(ev.w - fdec(mp[3]));
    reinterpret_cast<float4*>(g_wbuf)[e] = w;
    red_add_v4(g_den + d * 4, w);
}

__global__ __launch_bounds__(256) void k_rcp() {
    int i = blockIdx.x * 256 + threadIdx.x;
    if (i < NN * 4) g_den[i] = 1.0f / g_den[i];
}

// pass 3: head-folded aggregation. 16 threads per edge, each owns 4 output cols.
// hacc[dst,:] += sum_h alpha_h * z[src,h,:]
__global__ __launch_bounds__(256) void k_eagg(const int* __restrict__ ei) {
    int t = blockIdx.x * 256 + threadIdx.x;
    int e = t >> 4;
    if (e >= E_TOT) return;
    int g = t & 15;
    int s, d; edge_sd(e, ei, s, d);
    float4 w4 = reinterpret_cast<const float4*>(g_wbuf)[e];
    float4 r4 = *reinterpret_cast<const float4*>(g_den + d * 4);
    float a0 = w4.x * r4.x, a1 = w4.y * r4.y, a2 = w4.z * r4.z, a3 = w4.w * r4.w;
    const float4* zr = reinterpret_cast<const float4*>(g_z) + (size_t)s * 64;
    float4 z0 = __ldg(zr + g);
    float4 z1 = __ldg(zr + 16 + g);
    float4 z2 = __ldg(zr + 32 + g);
    float4 z3 = __ldg(zr + 48 + g);
    float4 acc;
    acc.x = fmaf(a3, z3.x, fmaf(a2, z2.x, fmaf(a1, z1.x, a0 * z0.x)));
    acc.y = fmaf(a3, z3.y, fmaf(a2, z2.y, fmaf(a1, z1.y, a0 * z0.y)));
    acc.z = fmaf(a3, z3.z, fmaf(a2, z2.z, fmaf(a1, z1.z, a0 * z0.z)));
    acc.w = fmaf(a3, z3.w, fmaf(a2, z2.w, fmaf(a1, z1.w, a0 * z0.w)));
    red_add_v4(g_hacc + (size_t)d * 64 + g * 4, acc);
}

// h = relu(mean_heads + bias)  (mean folded as 0.25 * head-sum)
__global__ __launch_bounds__(256) void k_final(const float* __restrict__ b) {
    int i = blockIdx.x * 256 + threadIdx.x;   // grid covers exactly N*64
    g_h[i] = fmaxf(0.f, fmaf(0.25f, g_hacc[i], b[i & 63]));
}

__global__ __launch_bounds__(256) void k_pool_init() {
    int i = blockIdx.x * 256 + threadIdx.x;   // grid covers G*64
    g_gsum[i] = 0.f;
    if (i < GG) g_cnt[i] = 0.f;
}

// global mean pool: vector reds into per-graph sums
__global__ __launch_bounds__(256) void k_pool(const int* __restrict__ batch) {
    int t = blockIdx.x * 256 + threadIdx.x;   // exactly N*16 threads
    int n = t >> 4, g = t & 15;
    int b = batch[n];
    float4 v = reinterpret_cast<const float4*>(g_h)[n * 16 + g];
    red_add_v4(g_gsum + b * 64 + g * 4, v);
    if (!g) atomicAdd(g_cnt + b, 1.0f);
}

__global__ __launch_bounds__(256) void k_pool_div() {
    int i = blockIdx.x * 256 + threadIdx.x;   // G*64
    g_pool[i] = g_gsum[i] / fmaxf(g_cnt[i >> 6], 1.0f);
}

// out[g, o] = <pooled[g,:], fc_w[o,:]> + fc_b[o]
// thread owns one output column o, weights in registers, pooled staged in smem.
__global__ __launch_bounds__(256) void k_fc(const float* __restrict__ fw,
                                            const float* __restrict__ fb,
                                            float* __restrict__ out) {
    __shared__ float ps[128 * 64];            // half of pooled (32 KB)
    int tid = threadIdx.x;
    int o = blockIdx.x * 256 + tid;
    float w[64];
    float bias = 0.f;
    if (o < OUTF) {
        bias = fb[o];
        const float4* wr = reinterpret_cast<const float4*>(fw + (size_t)o * 64);
#pragma unroll
        for (int k = 0; k < 16; k++) {
            float4 v = wr[k];
            w[4 * k] = v.x; w[4 * k + 1] = v.y; w[4 * k + 2] = v.z; w[4 * k + 3] = v.w;
        }
    }
    for (int half = 0; half < 2; half++) {
        __syncthreads();
        for (int i = tid; i < 128 * 16; i += 256)
            reinterpret_cast<float4*>(ps)[i] =
                reinterpret_cast<const float4*>(g_pool)[half * 2048 + i];
        __syncthreads();
        for (int gl = 0; gl < 128; gl++) {
            const float4* pr = reinterpret_cast<const float4*>(ps + gl * 64);
            float acc = bias;
#pragma unroll
            for (int k = 0; k < 16; k++) {
                float4 v = pr[k];
                acc = fmaf(v.x, w[4 * k], acc);
                acc = fmaf(v.y, w[4 * k + 1], acc);
                acc = fmaf(v.z, w[4 * k + 2], acc);
                acc = fmaf(v.w, w[4 * k + 3], acc);
            }
            if (o < OUTF) out[(size_t)(half * 128 + gl) * OUTF + o] = acc;
        }
    }
}

// ---------------- launch ----------------
extern "C" void kernel_launch(void* const* d_in, const int* in_sizes, int n_in,
                              void* d_out, int out_size) {
    const float* x     = (const float*)d_in[0];
    const int*   ei    = (const int*)  d_in[1];
    // d_in[2] = edge_attr (unused by reference)
    const int*   batch = (const int*)  d_in[3];
    const float* emb_w = (const float*)d_in[4];
    const float* emb_b = (const float*)d_in[5];
    const float* lin_w = (const float*)d_in[6];
    const float* att_s = (const float*)d_in[7];
    const float* att_d = (const float*)d_in[8];
    const float* gat_b = (const float*)d_in[9];
    const float* fc_w  = (const float*)d_in[10];
    const float* fc_b  = (const float*)d_in[11];
    float* out = (float*)d_out;

    k_embed<<<NN / 4, 256>>>(x, emb_w, emb_b);

    const int eb  = (E_TOT + 255) / 256;            // 3321
    const int agb = ((E_TOT * 16) + 255) / 256;     // 53125

    for (int l = 0; l < 3; l++) {
        k_zgemm <<<dim3(NN / 40, 2), 128>>>(lin_w + (size_t)l * 256 * 64);
        k_scores<<<(NN * 32) / 256, 256>>>(att_s + l * 256, att_d + l * 256);
        k_init  <<<NN * 64 / 256, 256>>>();
        k_emax  <<<eb, 256>>>(ei);
        k_esum  <<<eb, 256>>>(ei);
        k_rcp   <<<(NN * 4 + 255) / 256, 256>>>();
        k_eagg  <<<agb, 256>>>(ei);
        k_final <<<NN * 64 / 256, 256>>>(gat_b + l * 64);
    }

    k_pool_init<<<GG * 64 / 256, 256>>>();
    k_pool     <<<NN * 16 / 256, 256>>>(batch);
    k_pool_div <<<GG * 64 / 256, 256>>>();
    k_fc       <<<(OUTF + 255) / 256, 256>>>(fc_w, fc_b, out);
}

// round 4
// speedup vs baseline: 1.0593x; 1.0593x over previous
#include <cuda_runtime.h>

// ---------------- problem constants (fixed shapes) ----------------
#define NN      50000
#define E_REAL  800000
#define E_TOT   850000      // + N self loops
#define HF      64
#define GG      256
#define OUTF    326000
#define NEGS    0.2f

// ---------------- scratch (__device__ globals; no allocs) ----------------
__device__ float    g_h   [NN * HF];                 // 12.8 MB
__device__ float    g_z   [(size_t)NN * 256];        // 51.2 MB
__device__ float    g_as  [NN * 4];
__device__ float    g_ad  [NN * 4];
__device__ unsigned g_menc[NN * 4];
__device__ float    g_den [NN * 4];                  // becomes 1/denom
__device__ float    g_wbuf[(size_t)E_TOT * 4];       // 13.6 MB
__device__ float    g_hacc[NN * HF];                 // 12.8 MB
__device__ float    g_gsum[GG * HF];
__device__ float    g_cnt [GG];
__device__ float    g_pool[GG * HF];

// ---------------- helpers ----------------
__device__ __forceinline__ float lrelu(float v) { return v > 0.f ? v : NEGS * v; }

__device__ __forceinline__ unsigned fenc(float f) {
    unsigned u = __float_as_uint(f);
    return (u & 0x80000000u) ? ~u : (u | 0x80000000u);
}
__device__ __forceinline__ float fdec(unsigned u) {
    return (u & 0x80000000u) ? __uint_as_float(u ^ 0x80000000u) : __uint_as_float(~u);
}

__device__ __forceinline__ void red_add_v4(float* p, float4 v) {
    asm volatile("red.global.add.v4.f32 [%0], {%1,%2,%3,%4};"
                 :: "l"(p), "f"(v.x), "f"(v.y), "f"(v.z), "f"(v.w) : "memory");
}

// packed fp32x2 FMA (SASS FFMA2): acc = a*b + acc, elementwise on 2 floats
__device__ __forceinline__ void ffma2(unsigned long long& acc,
                                      unsigned long long a, unsigned long long b) {
    asm("fma.rn.f32x2 %0, %1, %2, %0;" : "+l"(acc) : "l"(a), "l"(b));
}
__device__ __forceinline__ float hadd2(unsigned long long v) {
    float lo, hi;
    asm("mov.b64 {%0,%1}, %2;" : "=f"(lo), "=f"(hi) : "l"(v));
    return lo + hi;
}

__device__ __forceinline__ void edge_sd(int e, const int* __restrict__ ei, int& s, int& d) {
    if (e < E_REAL) { s = ei[e]; d = ei[E_REAL + e]; }
    else            { s = e - E_REAL; d = s; }
}

__device__ __forceinline__ float4 edge_e(int s, int d) {
    float4 a = *reinterpret_cast<const float4*>(g_as + s * 4);
    float4 b = *reinterpret_cast<const float4*>(g_ad + d * 4);
    float4 r;
    r.x = lrelu(a.x + b.x); r.y = lrelu(a.y + b.y);
    r.z = lrelu(a.z + b.z); r.w = lrelu(a.w + b.w);
    return r;
}

// ---------------- kernels ----------------

// h = x @ emb_w^T + emb_b    (N x 128 -> N x 64). 4 nodes / 256-thread block.
__global__ __launch_bounds__(256) void k_embed(const float* __restrict__ x,
                                               const float* __restrict__ w,
                                               const float* __restrict__ b) {
    __shared__ float ws[64 * 129];   // +1 pad: conflict-free scalar reads
    __shared__ float xs[4 * 128];
    int tid = threadIdx.x;
    for (int i = tid; i < 64 * 128; i += 256)
        ws[(i >> 7) * 129 + (i & 127)] = w[i];
    int n0 = blockIdx.x * 4;
    for (int i = tid; i < 4 * 128; i += 256)
        xs[i] = x[n0 * 128 + i];
    __syncthreads();
    int j = tid & 63, ln = tid >> 6;
    const float* wr = ws + j * 129;
    const float* xr = xs + ln * 128;
    float acc = b[j];
#pragma unroll 16
    for (int k = 0; k < 128; k++) acc = fmaf(xr[k], wr[k], acc);
    g_h[(n0 + ln) * 64 + j] = acc;
}

// Fused: z = h @ lin_w^T  (N x 64 -> N x 256) + attention logits a_s/a_d.
// 256 threads; thread tid owns output column tid, weights register-resident.
// h rows broadcast from smem. Per-node warp reductions produce a_s/a_d.
#define ZNODES 50
__global__ __launch_bounds__(256) void k_zgemm_sc(const float* __restrict__ lw,
                                                  const float* __restrict__ aw_s,
                                                  const float* __restrict__ aw_d) {
    __shared__ __align__(16) float hs[ZNODES * 64];
    __shared__ float sc[2][ZNODES][4][2];     // [src/dst][node][head][warp-half]
    int tid = threadIdx.x;
    int n0 = blockIdx.x * ZNODES;

    // stage h rows
    for (int i = tid; i < ZNODES * 64; i += 256)
        hs[i] = g_h[n0 * 64 + i];

    // weights for this output column -> 32 packed regs
    unsigned long long w2[32];
    {
        const ulonglong2* wq = reinterpret_cast<const ulonglong2*>(lw + tid * 64);
#pragma unroll
        for (int k = 0; k < 16; k++) { ulonglong2 t = wq[k]; w2[2 * k] = t.x; w2[2 * k + 1] = t.y; }
    }
    float asw = aw_s[tid];          // att_src[h][d], h = tid>>6, d = tid & 63
    float adw = aw_d[tid];
    int ww   = tid >> 5;            // warp id: head = ww>>1, half = ww&1
    int lane = tid & 31;
    __syncthreads();

    float* zrow = g_z + (size_t)n0 * 256 + tid;
    for (int nl = 0; nl < ZNODES; nl++) {
        const ulonglong2* hq = reinterpret_cast<const ulonglong2*>(hs + nl * 64);
        unsigned long long a0 = 0ull, a1 = 0ull;
#pragma unroll
        for (int k = 0; k < 16; k++) {
            ulonglong2 hv = hq[k];
            ffma2(a0, hv.x, w2[2 * k]);
            ffma2(a1, hv.y, w2[2 * k + 1]);
        }
        float zv = hadd2(a0) + hadd2(a1);
        zrow[(size_t)nl * 256] = zv;

        float ps = zv * asw, pd = zv * adw;
#pragma unroll
        for (int o = 16; o; o >>= 1) {
            ps += __shfl_down_sync(0xffffffffu, ps, o);
            pd += __shfl_down_sync(0xffffffffu, pd, o);
        }
        if (!lane) { sc[0][nl][ww >> 1][ww & 1] = ps; sc[1][nl][ww >> 1][ww & 1] = pd; }
    }
    __syncthreads();
    for (int t = tid; t < 2 * ZNODES * 4; t += 256) {
        int arr = t >= ZNODES * 4;
        int u = arr ? t - ZNODES * 4 : t;
        int node = u >> 2, hh = u & 3;
        float v = sc[arr][node][hh][0] + sc[arr][node][hh][1];
        (arr ? g_ad : g_as)[(n0 + node) * 4 + hh] = v;
    }
}

// zero accumulators (run once before layer 0)
__global__ __launch_bounds__(256) void k_init0() {
    int i = blockIdx.x * 256 + threadIdx.x;   // grid covers N*64
    g_hacc[i] = 0.f;
    if (i < NN * 4) { g_menc[i] = 0u; g_den[i] = 0.f; }
}

// pass 1: segment max over dst (encoded atomicMax)
__global__ __launch_bounds__(256) void k_emax(const int* __restrict__ ei) {
    int e = blockIdx.x * 256 + threadIdx.x;
    if (e >= E_TOT) return;
    int s, d; edge_sd(e, ei, s, d);
    float4 ev = edge_e(s, d);
    unsigned* mp = g_menc + d * 4;
    atomicMax(mp + 0, fenc(ev.x));
    atomicMax(mp + 1, fenc(ev.y));
    atomicMax(mp + 2, fenc(ev.z));
    atomicMax(mp + 3, fenc(ev.w));
}

// pass 2: w = exp(e - m[dst]); store w; segment-sum denom (vector red)
__global__ __launch_bounds__(256) void k_esum(const int* __restrict__ ei) {
    int e = blockIdx.x * 256 + threadIdx.x;
    if (e >= E_TOT) return;
    int s, d; edge_sd(e, ei, s, d);
    float4 ev = edge_e(s, d);
    const unsigned* mp = g_menc + d * 4;
    float4 w;
    w.x = __expf(ev.x - fdec(mp[0]));
    w.y = __expf(ev.y - fdec(mp[1]));
    w.z = __expf(ev.z - fdec(mp[2]));
    w.w = __expf(ev.w - fdec(mp[3]));
    reinterpret_cast<float4*>(g_wbuf)[e] = w;
    red_add_v4(g_den + d * 4, w);
}

__global__ __launch_bounds__(256) void k_rcp() {
    int i = blockIdx.x * 256 + threadIdx.x;
    if (i < NN * 4) g_den[i] = 1.0f / g_den[i];
}

// pass 3: head-folded aggregation. 16 threads per edge, each owns 4 output cols.
__global__ __launch_bounds__(256) void k_eagg(const int* __restrict__ ei) {
    int t = blockIdx.x * 256 + threadIdx.x;
    int e = t >> 4;
    if (e >= E_TOT) return;
    int g = t & 15;
    int s, d; edge_sd(e, ei, s, d);
    float4 w4 = reinterpret_cast<const float4*>(g_wbuf)[e];
    float4 r4 = *reinterpret_cast<const float4*>(g_den + d * 4);
    float a0 = w4.x * r4.x, a1 = w4.y * r4.y, a2 = w4.z * r4.z, a3 = w4.w * r4.w;
    const float4* zr = reinterpret_cast<const float4*>(g_z) + (size_t)s * 64;
    float4 z0 = __ldg(zr + g);
    float4 z1 = __ldg(zr + 16 + g);
    float4 z2 = __ldg(zr + 32 + g);
    float4 z3 = __ldg(zr + 48 + g);
    float4 acc;
    acc.x = fmaf(a3, z3.x, fmaf(a2, z2.x, fmaf(a1, z1.x, a0 * z0.x)));
    acc.y = fmaf(a3, z3.y, fmaf(a2, z2.y, fmaf(a1, z1.y, a0 * z0.y)));
    acc.z = fmaf(a3, z3.z, fmaf(a2, z2.z, fmaf(a1, z1.z, a0 * z0.z)));
    acc.w = fmaf(a3, z3.w, fmaf(a2, z2.w, fmaf(a1, z1.w, a0 * z0.w)));
    red_add_v4(g_hacc + (size_t)d * 64 + g * 4, acc);
}

// h = relu(0.25*head_sum + bias), AND zero next layer's accumulators.
// If last layer, also zero pooling accumulators.
__global__ __launch_bounds__(256) void k_final(const float* __restrict__ b, int last) {
    int i = blockIdx.x * 256 + threadIdx.x;   // grid covers exactly N*64
    g_h[i] = fmaxf(0.f, fmaf(0.25f, g_hacc[i], b[i & 63]));
    g_hacc[i] = 0.f;
    if (i < NN * 4) { g_menc[i] = 0u; g_den[i] = 0.f; }
    if (last) {
        if (i < GG * 64) g_gsum[i] = 0.f;
        if (i < GG)      g_cnt[i]  = 0.f;
    }
}

// global mean pool: vector reds into per-graph sums
__global__ __launch_bounds__(256) void k_pool(const int* __restrict__ batch) {
    int t = blockIdx.x * 256 + threadIdx.x;   // exactly N*16 threads
    int n = t >> 4, g = t & 15;
    int b = batch[n];
    float4 v = reinterpret_cast<const float4*>(g_h)[n * 16 + g];
    red_add_v4(g_gsum + b * 64 + g * 4, v);
    if (!g) atomicAdd(g_cnt + b, 1.0f);
}

__global__ __launch_bounds__(256) void k_pool_div() {
    int i = blockIdx.x * 256 + threadIdx.x;   // G*64
    g_pool[i] = g_gsum[i] / fmaxf(g_cnt[i >> 6], 1.0f);
}

// out[g, o] = <pooled[g,:], fc_w[o,:]> + fc_b[o]
// thread owns output column o: weights in 32 packed regs, pooled broadcast from smem.
__global__ __launch_bounds__(256) void k_fc(const float* __restrict__ fw,
                                            const float* __restrict__ fb,
                                            float* __restrict__ out) {
    __shared__ __align__(16) float ps[128 * 64];   // half of pooled (32 KB)
    int tid = threadIdx.x;
    int o = blockIdx.x * 256 + tid;
    int valid = o < OUTF;
    int oc = valid ? o : 0;

    unsigned long long w2[32];
    {
        const ulonglong2* wq = reinterpret_cast<const ulonglong2*>(fw + (size_t)oc * 64);
#pragma unroll
        for (int k = 0; k < 16; k++) { ulonglong2 t = wq[k]; w2[2 * k] = t.x; w2[2 * k + 1] = t.y; }
    }
    float bias = valid ? fb[oc] : 0.f;

    for (int half = 0; half < 2; half++) {
        __syncthreads();
        for (int i = tid; i < 128 * 16; i += 256)
            reinterpret_cast<float4*>(ps)[i] =
                reinterpret_cast<const float4*>(g_pool)[half * 2048 + i];
        __syncthreads();
        for (int gl = 0; gl < 128; gl++) {
            const ulonglong2* pq = reinterpret_cast<const ulonglong2*>(ps + gl * 64);
            unsigned long long a0 = 0ull, a1 = 0ull;
#pragma unroll
            for (int k = 0; k < 16; k++) {
                ulonglong2 pv = pq[k];
                ffma2(a0, pv.x, w2[2 * k]);
                ffma2(a1, pv.y, w2[2 * k + 1]);
            }
            float acc = hadd2(a0) + hadd2(a1) + bias;
            if (valid) out[(size_t)(half * 128 + gl) * OUTF + o] = acc;
        }
    }
}

// ---------------- launch ----------------
extern "C" void kernel_launch(void* const* d_in, const int* in_sizes, int n_in,
                              void* d_out, int out_size) {
    const float* x     = (const float*)d_in[0];
    const int*   ei    = (const int*)  d_in[1];
    // d_in[2] = edge_attr (unused by reference)
    const int*   batch = (const int*)  d_in[3];
    const float* emb_w = (const float*)d_in[4];
    const float* emb_b = (const float*)d_in[5];
    const float* lin_w = (const float*)d_in[6];
    const float* att_s = (const float*)d_in[7];
    const float* att_d = (const float*)d_in[8];
    const float* gat_b = (const float*)d_in[9];
    const float* fc_w  = (const float*)d_in[10];
    const float* fc_b  = (const float*)d_in[11];
    float* out = (float*)d_out;

    k_embed<<<NN / 4, 256>>>(x, emb_w, emb_b);
    k_init0<<<NN * 64 / 256, 256>>>();

    const int eb  = (E_TOT + 255) / 256;            // 3321
    const int agb = ((E_TOT * 16) + 255) / 256;     // 53125

    for (int l = 0; l < 3; l++) {
        k_zgemm_sc<<<NN / ZNODES, 256>>>(lin_w + (size_t)l * 256 * 64,
                                         att_s + l * 256, att_d + l * 256);
        k_emax <<<eb, 256>>>(ei);
        k_esum <<<eb, 256>>>(ei);
        k_rcp  <<<(NN * 4 + 255) / 256, 256>>>();
        k_eagg <<<agb, 256>>>(ei);
        k_final<<<NN * 64 / 256, 256>>>(gat_b + l * 64, l == 2);
    }

    k_pool    <<<NN * 16 / 256, 256>>>(batch);
    k_pool_div<<<GG * 64 / 256, 256>>>();
    k_fc      <<<(OUTF + 255) / 256, 256>>>(fc_w, fc_b, out);
}

// round 6
// speedup vs baseline: 1.1325x; 1.0691x over previous
#include <cuda_runtime.h>

// ---------------- problem constants (fixed shapes) ----------------
#define NN      50000
#define E_REAL  800000
#define E_TOT   850000      // + N self loops
#define HF      64
#define GG      256
#define OUTF    326000
#define NEGS    0.2f

// ---------------- scratch (__device__ globals; no allocs) ----------------
__device__ float    g_h   [NN * HF];                 // 12.8 MB
__device__ float    g_z   [(size_t)NN * 256];        // 51.2 MB
__device__ float    g_as  [NN * 4];
__device__ float    g_ad  [NN * 4];
__device__ int      g_deg [NN];
__device__ int      g_rowptr[NN + 1];
__device__ int      g_wpos[NN];
__device__ int      g_csrc[E_TOT];                   // src ids sorted by dst
__device__ float    g_gsum[GG * HF];
__device__ float    g_cnt [GG];
__device__ float    g_pool[GG * HF];

// ---------------- helpers ----------------
__device__ __forceinline__ float lrelu(float v) { return v > 0.f ? v : NEGS * v; }

__device__ __forceinline__ void red_add_v4(float* p, float4 v) {
    asm volatile("red.global.add.v4.f32 [%0], {%1,%2,%3,%4};"
                 :: "l"(p), "f"(v.x), "f"(v.y), "f"(v.z), "f"(v.w) : "memory");
}

// packed fp32x2 FMA (SASS FFMA2)
__device__ __forceinline__ void ffma2(unsigned long long& acc,
                                      unsigned long long a, unsigned long long b) {
    asm("fma.rn.f32x2 %0, %1, %2, %0;" : "+l"(acc) : "l"(a), "l"(b));
}
__device__ __forceinline__ float hadd2(unsigned long long v) {
    float lo, hi;
    asm("mov.b64 {%0,%1}, %2;" : "=f"(lo), "=f"(hi) : "l"(v));
    return lo + hi;
}

// exp(e) with overflow clamp; logits here are O(0.1) so clamp never binds
__device__ __forceinline__ float sexp(float e) { return __expf(fminf(e, 60.f)); }

__device__ __forceinline__ void edge_sd(int e, const int* __restrict__ ei, int& s, int& d) {
    if (e < E_REAL) { s = ei[e]; d = ei[E_REAL + e]; }
    else            { s = e - E_REAL; d = s; }
}

// ---------------- CSR build (topology constant across layers) ----------------

__global__ __launch_bounds__(256) void k_zerocsr() {
    int i = blockIdx.x * 256 + threadIdx.x;
    if (i < NN) g_deg[i] = 0;
    if (i < GG * 64) g_gsum[i] = 0.f;
    if (i < GG) g_cnt[i] = 0.f;
}

__global__ __launch_bounds__(256) void k_hist(const int* __restrict__ ei) {
    int e = blockIdx.x * 256 + threadIdx.x;
    if (e >= E_TOT) return;
    int s, d; edge_sd(e, ei, s, d);
    atomicAdd(&g_deg[d], 1);
}

// single-block exclusive scan of g_deg -> g_rowptr, g_wpos
#define SCAN_T 1024
#define SCAN_C ((NN + SCAN_T - 1) / SCAN_T)   // 49
__global__ __launch_bounds__(SCAN_T) void k_scan() {
    __shared__ int part[SCAN_T];
    int t = threadIdx.x;
    int b = t * SCAN_C, e = min(b + SCAN_C, NN);
    int sum = 0;
    for (int i = b; i < e; i++) sum += g_deg[i];
    part[t] = sum;
    __syncthreads();
    for (int off = 1; off < SCAN_T; off <<= 1) {
        int v = (t >= off) ? part[t - off] : 0;
        __syncthreads();
        part[t] += v;
        __syncthreads();
    }
    int run = part[t] - sum;   // exclusive prefix
    for (int i = b; i < e; i++) {
        g_rowptr[i] = run;
        g_wpos[i] = run;
        run += g_deg[i];
    }
    if (t == SCAN_T - 1) g_rowptr[NN] = E_TOT;
}

__global__ __launch_bounds__(256) void k_scatter(const int* __restrict__ ei) {
    int e = blockIdx.x * 256 + threadIdx.x;
    if (e >= E_TOT) return;
    int s, d; edge_sd(e, ei, s, d);
    int pos = atomicAdd(&g_wpos[d], 1);
    g_csrc[pos] = s;
}

// ---------------- dense kernels ----------------

// h = x @ emb_w^T + emb_b    (N x 128 -> N x 64). 4 nodes / 256-thread block.
__global__ __launch_bounds__(256) void k_embed(const float* __restrict__ x,
                                               const float* __restrict__ w,
                                               const float* __restrict__ b) {
    __shared__ float ws[64 * 129];
    __shared__ float xs[4 * 128];
    int tid = threadIdx.x;
    for (int i = tid; i < 64 * 128; i += 256)
        ws[(i >> 7) * 129 + (i & 127)] = w[i];
    int n0 = blockIdx.x * 4;
    for (int i = tid; i < 4 * 128; i += 256)
        xs[i] = x[n0 * 128 + i];
    __syncthreads();
    int j = tid & 63, ln = tid >> 6;
    const float* wr = ws + j * 129;
    const float* xr = xs + ln * 128;
    float acc = b[j];
#pragma unroll 16
    for (int k = 0; k < 128; k++) acc = fmaf(xr[k], wr[k], acc);
    g_h[(n0 + ln) * 64 + j] = acc;
}

// Fused: z = h @ lin_w^T (N x 64 -> N x 256) + attention logits a_s/a_d.
#define ZNODES 50
__global__ __launch_bounds__(256) void k_zgemm_sc(const float* __restrict__ lw,
                                                  const float* __restrict__ aw_s,
                                                  const float* __restrict__ aw_d) {
    __shared__ __align__(16) float hs[ZNODES * 64];
    __shared__ float sc[2][ZNODES][4][2];
    int tid = threadIdx.x;
    int n0 = blockIdx.x * ZNODES;

    for (int i = tid; i < ZNODES * 64; i += 256)
        hs[i] = g_h[n0 * 64 + i];

    unsigned long long w2[32];
    {
        const ulonglong2* wq = reinterpret_cast<const ulonglong2*>(lw + tid * 64);
#pragma unroll
        for (int k = 0; k < 16; k++) { ulonglong2 t = wq[k]; w2[2 * k] = t.x; w2[2 * k + 1] = t.y; }
    }
    float asw = aw_s[tid];
    float adw = aw_d[tid];
    int ww = tid >> 5, lane = tid & 31;
    __syncthreads();

    float* zrow = g_z + (size_t)n0 * 256 + tid;
    for (int nl = 0; nl < ZNODES; nl++) {
        const ulonglong2* hq = reinterpret_cast<const ulonglong2*>(hs + nl * 64);
        unsigned long long a0 = 0ull, a1 = 0ull;
#pragma unroll
        for (int k = 0; k < 16; k++) {
            ulonglong2 hv = hq[k];
            ffma2(a0, hv.x, w2[2 * k]);
            ffma2(a1, hv.y, w2[2 * k + 1]);
        }
        float zv = hadd2(a0) + hadd2(a1);
        zrow[(size_t)nl * 256] = zv;

        float ps = zv * asw, pd = zv * adw;
#pragma unroll
        for (int o = 16; o; o >>= 1) {
            ps += __shfl_down_sync(0xffffffffu, ps, o);
            pd += __shfl_down_sync(0xffffffffu, pd, o);
        }
        if (!lane) { sc[0][nl][ww >> 1][ww & 1] = ps; sc[1][nl][ww >> 1][ww & 1] = pd; }
    }
    __syncthreads();
    for (int t = tid; t < 2 * ZNODES * 4; t += 256) {
        int arr = t >= ZNODES * 4;
        int u = arr ? t - ZNODES * 4 : t;
        int node = u >> 2, hh = u & 3;
        float v = sc[arr][node][hh][0] + sc[arr][node][hh][1];
        (arr ? g_ad : g_as)[(n0 + node) * 4 + hh] = v;
    }
}

// ---------------- fused GAT aggregation: one warp per dst ----------------
// phase A: denom_h = sum_e exp(lrelu(a_s[src]+a_d[dst]))   (registers + shfl)
// phase B: h[dst] = relu(0.25 * sum_e sum_h alpha_eh * z[src,h,:] + bias)
#define AGG_WARPS 8
__global__ __launch_bounds__(256) void k_gatagg(const float* __restrict__ bias) {
    __shared__ int   s_src[AGG_WARPS][32];
    __shared__ float4 s_al[AGG_WARPS][32];
    int warp = threadIdx.x >> 5, lane = threadIdx.x & 31;
    int dst = blockIdx.x * AGG_WARPS + warp;
    if (dst >= NN) return;

    int beg = g_rowptr[dst], end = g_rowptr[dst + 1];
    float4 ad = *reinterpret_cast<const float4*>(g_ad + dst * 4);

    // phase A: per-head denominators
    float4 den = make_float4(0.f, 0.f, 0.f, 0.f);
    for (int i = beg + lane; i < end; i += 32) {
        int s = g_csrc[i];
        float4 as = *reinterpret_cast<const float4*>(g_as + s * 4);
        den.x += sexp(lrelu(as.x + ad.x));
        den.y += sexp(lrelu(as.y + ad.y));
        den.z += sexp(lrelu(as.z + ad.z));
        den.w += sexp(lrelu(as.w + ad.w));
    }
#pragma unroll
    for (int o = 16; o; o >>= 1) {
        den.x += __shfl_xor_sync(0xffffffffu, den.x, o);
        den.y += __shfl_xor_sync(0xffffffffu, den.y, o);
        den.z += __shfl_xor_sync(0xffffffffu, den.z, o);
        den.w += __shfl_xor_sync(0xffffffffu, den.w, o);
    }
    float4 rd = make_float4(1.f / den.x, 1.f / den.y, 1.f / den.z, 1.f / den.w);

    // phase B: weighted gather; lane owns output cols 2*lane, 2*lane+1
    float acc0 = 0.f, acc1 = 0.f;
    for (int base = beg; base < end; base += 32) {
        int i = base + lane;
        if (i < end) {
            int s = g_csrc[i];
            float4 as = *reinterpret_cast<const float4*>(g_as + s * 4);
            float4 a;
            a.x = sexp(lrelu(as.x + ad.x)) * rd.x;
            a.y = sexp(lrelu(as.y + ad.y)) * rd.y;
            a.z = sexp(lrelu(as.z + ad.z)) * rd.z;
            a.w = sexp(lrelu(as.w + ad.w)) * rd.w;
            s_src[warp][lane] = s;
            s_al[warp][lane] = a;
        }
        __syncwarp();
        int cnt = min(32, end - base);
        for (int j = 0; j < cnt; j++) {
            int s = s_src[warp][j];
            float4 a = s_al[warp][j];
            const float2* zp = reinterpret_cast<const float2*>(g_z + (size_t)s * 256) + lane;
            float2 z0 = __ldg(zp);
            float2 z1 = __ldg(zp + 32);
            float2 z2 = __ldg(zp + 64);
            float2 z3 = __ldg(zp + 96);
            acc0 += a.x * z0.x + a.y * z1.x + a.z * z2.x + a.w * z3.x;
            acc1 += a.x * z0.y + a.y * z1.y + a.z * z2.y + a.w * z3.y;
        }
        __syncwarp();
    }
    float2 bv = *reinterpret_cast<const float2*>(bias + 2 * lane);
    float2 out;
    out.x = fmaxf(0.f, fmaf(0.25f, acc0, bv.x));
    out.y = fmaxf(0.f, fmaf(0.25f, acc1, bv.y));
    *reinterpret_cast<float2*>(g_h + dst * 64 + 2 * lane) = out;
}

// ---------------- pooling + FC ----------------

__global__ __launch_bounds__(256) void k_pool(const int* __restrict__ batch) {
    int t = blockIdx.x * 256 + threadIdx.x;   // exactly N*16 threads
    int n = t >> 4, g = t & 15;
    int b = batch[n];
    float4 v = reinterpret_cast<const float4*>(g_h)[n * 16 + g];
    red_add_v4(g_gsum + b * 64 + g * 4, v);
    if (!g) atomicAdd(g_cnt + b, 1.0f);
}

__global__ __launch_bounds__(256) void k_pool_div() {
    int i = blockIdx.x * 256 + threadIdx.x;   // G*64
    g_pool[i] = g_gsum[i] / fmaxf(g_cnt[i >> 6], 1.0f);
}

__global__ __launch_bounds__(256) void k_fc(const float* __restrict__ fw,
                                            const float* __restrict__ fb,
                                            float* __restrict__ out) {
    __shared__ __align__(16) float ps[128 * 64];
    int tid = threadIdx.x;
    int o = blockIdx.x * 256 + tid;
    int valid = o < OUTF;
    int oc = valid ? o : 0;

    unsigned long long w2[32];
    {
        const ulonglong2* wq = reinterpret_cast<const ulonglong2*>(fw + (size_t)oc * 64);
#pragma unroll
        for (int k = 0; k < 16; k++) { ulonglong2 t = wq[k]; w2[2 * k] = t.x; w2[2 * k + 1] = t.y; }
    }
    float bias = valid ? fb[oc] : 0.f;

    for (int half = 0; half < 2; half++) {
        __syncthreads();
        for (int i = tid; i < 128 * 16; i += 256)
            reinterpret_cast<float4*>(ps)[i] =
                reinterpret_cast<const float4*>(g_pool)[half * 2048 + i];
        __syncthreads();
        for (int gl = 0; gl < 128; gl++) {
            const ulonglong2* pq = reinterpret_cast<const ulonglong2*>(ps + gl * 64);
            unsigned long long a0 = 0ull, a1 = 0ull;
#pragma unroll
            for (int k = 0; k < 16; k++) {
                ulonglong2 pv = pq[k];
                ffma2(a0, pv.x, w2[2 * k]);
                ffma2(a1, pv.y, w2[2 * k + 1]);
            }
            float acc = hadd2(a0) + hadd2(a1) + bias;
            if (valid) out[(size_t)(half * 128 + gl) * OUTF + o] = acc;
        }
    }
}

// ---------------- launch ----------------
extern "C" void kernel_launch(void* const* d_in, const int* in_sizes, int n_in,
                              void* d_out, int out_size) {
    const float* x     = (const float*)d_in[0];
    const int*   ei    = (const int*)  d_in[1];
    // d_in[2] = edge_attr (unused by reference)
    const int*   batch = (const int*)  d_in[3];
    const float* emb_w = (const float*)d_in[4];
    const float* emb_b = (const float*)d_in[5];
    const float* lin_w = (const float*)d_in[6];
    const float* att_s = (const float*)d_in[7];
    const float* att_d = (const float*)d_in[8];
    const float* gat_b = (const float*)d_in[9];
    const float* fc_w  = (const float*)d_in[10];
    const float* fc_b  = (const float*)d_in[11];
    float* out = (float*)d_out;

    const int eb = (E_TOT + 255) / 256;   // 3321

    k_embed  <<<NN / 4, 256>>>(x, emb_w, emb_b);
    k_zerocsr<<<(NN + 255) / 256, 256>>>();
    k_hist   <<<eb, 256>>>(ei);
    k_scan   <<<1, SCAN_T>>>();
    k_scatter<<<eb, 256>>>(ei);

    for (int l = 0; l < 3; l++) {
        k_zgemm_sc<<<NN / ZNODES, 256>>>(lin_w + (size_t)l * 256 * 64,
                                         att_s + l * 256, att_d + l * 256);
        k_gatagg  <<<(NN + AGG_WARPS - 1) / AGG_WARPS, 256>>>(gat_b + l * 64);
    }

    k_pool    <<<NN * 16 / 256, 256>>>(batch);
    k_pool_div<<<GG * 64 / 256, 256>>>();
    k_fc      <<<(OUTF + 255) / 256, 256>>>(fc_w, fc_b, out);
}